// round 16
// baseline (speedup 1.0000x reference)
#include <cuda_runtime.h>
#include <cuda_bf16.h>
#include <math.h>
#include <stdint.h>

#define SEQ 2048
#define EMB 1024
#define NH  16
#define HD  64

typedef unsigned long long u64;

// Scratch (device globals — no allocation allowed)
__device__ __nv_bfloat16 g_Q[NH * SEQ * HD];
__device__ __nv_bfloat16 g_K[NH * SEQ * HD];
__device__ __nv_bfloat16 g_V[NH * SEQ * HD];
// g_S: TILED layout [NH][32 qt][32 kt][64*64], scores then exp values
__device__ __nv_bfloat16 g_S[(size_t)NH * SEQ * SEQ];
__device__ float g_L[NH * SEQ];          // per-row softmax denominators
__device__ float g_attn[SEQ * EMB];

__device__ __forceinline__ float bf16r(float v) {
    return __bfloat162float(__float2bfloat16(v));
}
__device__ __forceinline__ uint32_t f2tf32(float x) {
    uint32_t r;
    asm("cvt.rna.tf32.f32 %0, %1;" : "=r"(r) : "f"(x));
    return r;
}

// ---------------- packed f32x2 fma (Blackwell FFMA2) ----------------
__device__ __forceinline__ void fma2(u64& d, u64 a, u64 b) {
    asm("fma.rn.f32x2 %0, %1, %2, %0;" : "+l"(d) : "l"(a), "l"(b));
}
__device__ __forceinline__ u64 bcast2(float v) {
    u64 r; asm("mov.b64 %0, {%1, %2};" : "=l"(r) : "f"(v), "f"(v)); return r;
}
__device__ __forceinline__ void unpack2(u64 p, float& lo, float& hi) {
    asm("mov.b64 {%0, %1}, %2;" : "=f"(lo), "=f"(hi) : "l"(p));
}

// ---------------- mma.sync helpers ----------------
__device__ __forceinline__ uint32_t smem_u32(const void* p) {
    return (uint32_t)__cvta_generic_to_shared(p);
}
__device__ __forceinline__ void ldsm_x4(uint32_t& a0, uint32_t& a1,
                                        uint32_t& a2, uint32_t& a3, uint32_t addr) {
    asm volatile("ldmatrix.sync.aligned.m8n8.x4.shared.b16 {%0,%1,%2,%3}, [%4];\n"
                 : "=r"(a0), "=r"(a1), "=r"(a2), "=r"(a3) : "r"(addr));
}
__device__ __forceinline__ void ldsm_x2(uint32_t& b0, uint32_t& b1, uint32_t addr) {
    asm volatile("ldmatrix.sync.aligned.m8n8.x2.shared.b16 {%0,%1}, [%2];\n"
                 : "=r"(b0), "=r"(b1) : "r"(addr));
}
__device__ __forceinline__ void ldsm_x2_t(uint32_t& b0, uint32_t& b1, uint32_t addr) {
    asm volatile("ldmatrix.sync.aligned.m8n8.x2.trans.shared.b16 {%0,%1}, [%2];\n"
                 : "=r"(b0), "=r"(b1) : "r"(addr));
}
__device__ __forceinline__ void mma16816(float& d0, float& d1, float& d2, float& d3,
                                         uint32_t a0, uint32_t a1, uint32_t a2, uint32_t a3,
                                         uint32_t b0, uint32_t b1) {
    asm volatile("mma.sync.aligned.m16n8k16.row.col.f32.bf16.bf16.f32 "
                 "{%0,%1,%2,%3},{%4,%5,%6,%7},{%8,%9},{%0,%1,%2,%3};\n"
                 : "+f"(d0), "+f"(d1), "+f"(d2), "+f"(d3)
                 : "r"(a0), "r"(a1), "r"(a2), "r"(a3), "r"(b0), "r"(b1));
}
__device__ __forceinline__ void mma_tf32(float* d, const uint32_t* a,
                                         const uint32_t* b) {
    asm volatile("mma.sync.aligned.m16n8k8.row.col.f32.tf32.tf32.f32 "
                 "{%0,%1,%2,%3},{%4,%5,%6,%7},{%8,%9},{%0,%1,%2,%3};\n"
                 : "+f"(d[0]), "+f"(d[1]), "+f"(d[2]), "+f"(d[3])
                 : "r"(a[0]), "r"(a[1]), "r"(a[2]), "r"(a[3]), "r"(b[0]), "r"(b[1]));
}

// ---------------- cp.async helpers ----------------
__device__ __forceinline__ void cp_async16(uint32_t smem_addr, const void* gptr) {
    asm volatile("cp.async.cg.shared.global [%0], [%1], 16;\n"
                 :: "r"(smem_addr), "l"(gptr));
}
__device__ __forceinline__ void cp_commit() {
    asm volatile("cp.async.commit_group;\n" ::: "memory");
}
__device__ __forceinline__ void cp_wait0() {
    asm volatile("cp.async.wait_group 0;\n" ::: "memory");
}
__device__ __forceinline__ void bar_sync(int id) {
    asm volatile("bar.sync %0, 128;\n" :: "r"(id) : "memory");
}

// ---------------------------------------------------------------------------
// Projection body — byte-identical math to round-15 proj kernel (sequential-K
// FFMA2 chains, conflict-free B reads, Kc=8 double buffer, reg prefetch).
// As/Bs are 2*8*128 float arrays in (dynamic or static) shared memory.
// ---------------------------------------------------------------------------
__device__ __forceinline__ void proj_body(
    const float* __restrict__ x, const float* __restrict__ W,
    const float* __restrict__ bias, __nv_bfloat16* out,
    int bx, int by, float* As, float* Bs)
{
    const int tid = threadIdx.x;
    const int tx = tid & 15, ty = tid >> 4;
    const int bM = by * 128, bN = bx * 128;

    const int ar = tid >> 1, ac = (tid & 1) * 4;
    const int br = tid >> 5, bc = (tid & 31) * 4;

    u64 acc2[8][4] = {};

    float4 pa = *(const float4*)(x + (size_t)(bM + ar) * EMB + ac);
    float4 pb = *(const float4*)(W + (size_t)br * EMB + bN + bc);

    for (int k0 = 0; k0 < EMB; k0 += 8) {
        const int b = (k0 >> 3) & 1;
        float* Ab = As + b * 8 * 128;
        float* Bb = Bs + b * 8 * 128;
        Ab[(ac + 0) * 128 + ar] = pa.x; Ab[(ac + 1) * 128 + ar] = pa.y;
        Ab[(ac + 2) * 128 + ar] = pa.z; Ab[(ac + 3) * 128 + ar] = pa.w;
        *(float4*)&Bb[br * 128 + bc] = pb;
        __syncthreads();

        if (k0 + 8 < EMB) {
            pa = *(const float4*)(x + (size_t)(bM + ar) * EMB + k0 + 8 + ac);
            pb = *(const float4*)(W + (size_t)(k0 + 8 + br) * EMB + bN + bc);
        }

        #pragma unroll
        for (int kk = 0; kk < 8; kk++) {
            float a[8];
            *(float4*)&a[0]  = *(float4*)&Ab[kk * 128 + ty * 8];
            *(float4*)&a[4]  = *(float4*)&Ab[kk * 128 + ty * 8 + 4];
            float4 b4a = *(float4*)&Bb[kk * 128 + tx * 4];
            float4 b4b = *(float4*)&Bb[kk * 128 + tx * 4 + 64];
            u64 bb2[4];
            bb2[0] = ((u64*)&b4a)[0];
            bb2[1] = ((u64*)&b4a)[1];
            bb2[2] = ((u64*)&b4b)[0];
            bb2[3] = ((u64*)&b4b)[1];
            #pragma unroll
            for (int i = 0; i < 8; i++) {
                u64 ai = bcast2(a[i]);
                #pragma unroll
                for (int jp = 0; jp < 4; jp++)
                    fma2(acc2[i][jp], ai, bb2[jp]);
            }
        }
        __syncthreads();
    }

    #pragma unroll
    for (int i = 0; i < 8; i++) {
        int m = bM + ty * 8 + i;
        #pragma unroll
        for (int jp = 0; jp < 4; jp++) {
            float v0, v1;
            unpack2(acc2[i][jp], v0, v1);
            int n = bN + tx * 4 + (jp >> 1) * 64 + (jp & 1) * 2;
            float r0 = v0 + bias[n];
            float r1 = v1 + bias[n + 1];
            out[(size_t)(n >> 6) * SEQ * HD + (size_t)m * HD + (n & 63)] =
                __float2bfloat16(r0);
            out[(size_t)((n + 1) >> 6) * SEQ * HD + (size_t)m * HD + ((n + 1) & 63)] =
                __float2bfloat16(r1);
        }
    }
}

// Q/K projections (z = 0,1)
__global__ __launch_bounds__(256) void proj_qk_kernel(
    const float* __restrict__ x,
    const float* __restrict__ Wq, const float* __restrict__ bq,
    const float* __restrict__ Wk, const float* __restrict__ bk)
{
    __shared__ float As[2 * 8 * 128];
    __shared__ float Bs[2 * 8 * 128];
    if (blockIdx.z == 0)
        proj_body(x, Wq, bq, g_Q, blockIdx.x, blockIdx.y, As, Bs);
    else
        proj_body(x, Wk, bk, g_K, blockIdx.x, blockIdx.y, As, Bs);
}

// ---------------------------------------------------------------------------
// Attention phase A (scores + softmax stats) — byte-identical math to the
// round-15 ph1+ph2; L goes to g_L instead of smem.
// ---------------------------------------------------------------------------
__device__ __forceinline__ void stage_tile(uint32_t dst, const __nv_bfloat16* src,
                                           int wtid) {
    #pragma unroll
    for (int u = 0; u < 4; u++) {
        int idx = wtid + u * 128;
        int r = idx >> 3, s = idx & 7;
        cp_async16(dst + (uint32_t)((r * 72 + s * 8) * 2), src + r * 64 + s * 8);
    }
}

__device__ void attnA_qtile(
    int qt, int h, __nv_bfloat16* Qs, __nv_bfloat16* KV2,
    float* mrow, float* psum, int wtid, int barid)
{
    const int lane = wtid & 31;
    const int warp = wtid >> 5;
    const int r0   = warp * 16;

    const size_t qbase = ((size_t)h * SEQ + (size_t)qt * 64) * HD;
    const size_t tile0 = (((size_t)h * 32 + qt) * 32) * 4096;
    const __nv_bfloat16* Kh = g_K + (size_t)h * SEQ * HD;

    const uint32_t kvb0 = smem_u32(KV2);
    const uint32_t kvb1 = kvb0 + 64 * 72 * 2;

    for (int idx = wtid; idx < 64 * 8; idx += 128) {
        int r = idx >> 3, s = idx & 7;
        *(uint4*)&Qs[r * 72 + s * 8] = *(const uint4*)&g_Q[qbase + r * 64 + s * 8];
    }
    bar_sync(barid);

    uint32_t aq[4][4];
    {
        const uint32_t qb = smem_u32(Qs);
        #pragma unroll
        for (int ks = 0; ks < 4; ks++) {
            uint32_t addr = qb +
                (uint32_t)((r0 + (lane & 7) + ((lane >> 3) & 1) * 8) * 144 +
                           ((lane >> 4) * 16) + ks * 32);
            ldsm_x4(aq[ks][0], aq[ks][1], aq[ks][2], aq[ks][3], addr);
        }
    }

    // ---- PHASE 1: S -> g_S tiles, running row max ----
    float rm0 = -INFINITY, rm1 = -INFINITY;
    const int rA = r0 + (lane >> 2);

    stage_tile(kvb0, Kh, wtid);
    cp_commit();

    for (int kt = 0; kt <= qt; kt++) {
        cp_wait0();
        bar_sync(barid);
        const uint32_t kvb = (kt & 1) ? kvb1 : kvb0;
        if (kt < qt) {
            stage_tile((kt & 1) ? kvb0 : kvb1, Kh + (size_t)(kt + 1) * 64 * HD, wtid);
            cp_commit();
        }

        const size_t tb = tile0 + (size_t)kt * 4096;
        const bool diag = (kt == qt);
        #pragma unroll
        for (int nt = 0; nt < 8; nt++) {
            float c0 = 0.f, c1 = 0.f, c2 = 0.f, c3 = 0.f;
            #pragma unroll
            for (int ks = 0; ks < 4; ks++) {
                int l2 = lane & 15;
                uint32_t addr = kvb +
                    (uint32_t)((nt * 8 + (l2 & 7)) * 144 + (l2 >> 3) * 16 + ks * 32);
                uint32_t b0, b1;
                ldsm_x2(b0, b1, addr);
                mma16816(c0, c1, c2, c3,
                         aq[ks][0], aq[ks][1], aq[ks][2], aq[ks][3], b0, b1);
            }
            const int cc = nt * 8 + (lane & 3) * 2;
            float s00 = bf16r(c0) * 0.5f;
            float s01 = bf16r(c1) * 0.5f;
            float s10 = bf16r(c2) * 0.5f;
            float s11 = bf16r(c3) * 0.5f;
            if (diag) {
                if (cc     > rA)     s00 = -INFINITY;
                if (cc + 1 > rA)     s01 = -INFINITY;
                if (cc     > rA + 8) s10 = -INFINITY;
                if (cc + 1 > rA + 8) s11 = -INFINITY;
            }
            rm0 = fmaxf(rm0, fmaxf(s00, s01));
            rm1 = fmaxf(rm1, fmaxf(s10, s11));
            __nv_bfloat162 p0; p0.x = __float2bfloat16(s00); p0.y = __float2bfloat16(s01);
            __nv_bfloat162 p1; p1.x = __float2bfloat16(s10); p1.y = __float2bfloat16(s11);
            *(uint32_t*)&g_S[tb + (size_t)rA * 64 + cc]       = *(uint32_t*)&p0;
            *(uint32_t*)&g_S[tb + (size_t)(rA + 8) * 64 + cc] = *(uint32_t*)&p1;
        }
    }
    rm0 = fmaxf(rm0, __shfl_xor_sync(0xFFFFFFFFu, rm0, 1));
    rm0 = fmaxf(rm0, __shfl_xor_sync(0xFFFFFFFFu, rm0, 2));
    rm1 = fmaxf(rm1, __shfl_xor_sync(0xFFFFFFFFu, rm1, 1));
    rm1 = fmaxf(rm1, __shfl_xor_sync(0xFFFFFFFFu, rm1, 2));
    if ((lane & 3) == 0) {
        mrow[rA]     = rm0;
        mrow[rA + 8] = rm1;
    }
    bar_sync(barid);

    // ---- PHASE 2: e -> g_S; L = bf16(sum_f32 e) -> g_L ----
    for (int rb = 0; rb < 64; rb += 32) {
        const int r = rb + (wtid >> 2), seg = wtid & 3;
        const float m = mrow[r];
        float part = 0.f;
        for (int ktt = 0; ktt <= qt; ktt++) {
            __nv_bfloat16* tp = &g_S[tile0 + (size_t)ktt * 4096 + (size_t)r * 64];
            #pragma unroll 4
            for (int c = seg; c < 64; c += 4) {
                float s = __bfloat162float(tp[c]);
                float t = bf16r(s - m);
                float e = bf16r(expf(t));
                part += e;
                tp[c] = __float2bfloat16(e);
            }
        }
        psum[r * 4 + seg] = part;
    }
    bar_sync(barid);
    if (wtid < 64) {
        float L32 = ((psum[wtid * 4 + 0] + psum[wtid * 4 + 1]) +
                      psum[wtid * 4 + 2]) + psum[wtid * 4 + 3];
        g_L[h * SEQ + qt * 64 + wtid] = bf16r(L32);
    }
}

// per-WG smem for attnA: Qs 9216, KV2 18432, mrow 256, psum 1024 = 28928 B
#define WGA_SMEM (9216 + 18432 + 256 + 1024)

// ---------------------------------------------------------------------------
// Fused kernel: blocks 0..255 = attnA (2 WGs, paired q-tiles);
//               blocks 256..383 = V projection tiles (fills attnA's idle slots)
// attnA never reads g_V; projV never touches g_S/g_L.
// ---------------------------------------------------------------------------
__global__ __launch_bounds__(256) void fused_attnA_projV(
    const float* __restrict__ x,
    const float* __restrict__ Wv, const float* __restrict__ bv)
{
    extern __shared__ char dyn_smem[];
    const int b = blockIdx.x;
    if (b < 256) {
        const int wg   = threadIdx.x >> 7;
        const int wtid = threadIdx.x & 127;
        char* base = dyn_smem + wg * WGA_SMEM;
        __nv_bfloat16* Qs  = (__nv_bfloat16*)base;
        __nv_bfloat16* KV2 = (__nv_bfloat16*)(base + 9216);
        float* mrow = (float*)(base + 9216 + 18432);
        float* psum = mrow + 64;
        const int h  = b >> 4;
        const int qp = b & 15;
        const int qt = wg ? (31 - qp) : qp;
        attnA_qtile(qt, h, Qs, KV2, mrow, psum, wtid, wg + 1);
    } else {
        const int idx = b - 256;            // 128 tiles: 8 x 16
        float* As = (float*)dyn_smem;
        float* Bs = As + 2 * 8 * 128;
        proj_body(x, Wv, bv, g_V, idx & 7, idx >> 3, As, Bs);
    }
}

// ---------------------------------------------------------------------------
// Attention phase B (p = bf16(e * 1/L), O = P @ V) — byte-identical math.
// ---------------------------------------------------------------------------
__device__ void attnB_qtile(
    int qt, int h, __nv_bfloat16* KV2, int wtid, int barid)
{
    const int lane = wtid & 31;
    const int warp = wtid >> 5;
    const int r0   = warp * 16;
    const int rA   = r0 + (lane >> 2);

    const size_t tile0 = (((size_t)h * 32 + qt) * 32) * 4096;
    const __nv_bfloat16* Vh = g_V + (size_t)h * SEQ * HD;

    const uint32_t kvb0 = smem_u32(KV2);
    const uint32_t kvb1 = kvb0 + 64 * 72 * 2;

    const float rL0 = 1.0f / g_L[h * SEQ + qt * 64 + rA];
    const float rL1 = 1.0f / g_L[h * SEQ + qt * 64 + rA + 8];

    float o[8][4];
    #pragma unroll
    for (int nt = 0; nt < 8; nt++)
        #pragma unroll
        for (int i = 0; i < 4; i++) o[nt][i] = 0.f;

    stage_tile(kvb0, Vh, wtid);
    cp_commit();

    for (int kt = 0; kt <= qt; kt++) {
        cp_wait0();
        bar_sync(barid);
        const uint32_t kvb = (kt & 1) ? kvb1 : kvb0;
        if (kt < qt) {
            stage_tile((kt & 1) ? kvb0 : kvb1, Vh + (size_t)(kt + 1) * 64 * HD, wtid);
            cp_commit();
        }

        const size_t tb  = tile0 + (size_t)kt * 4096;
        const size_t rowA = tb + (size_t)rA * 64;
        const size_t rowB = tb + (size_t)(rA + 8) * 64;

        uint32_t pa[4][4];
        #pragma unroll
        for (int ks = 0; ks < 4; ks++) {
            const int col = ks * 16 + (lane & 3) * 2;
            #pragma unroll
            for (int half = 0; half < 2; half++) {
                uint32_t sA = *(const uint32_t*)&g_S[rowA + col + half * 8];
                uint32_t sB = *(const uint32_t*)&g_S[rowB + col + half * 8];
                __nv_bfloat162 eA = *(__nv_bfloat162*)&sA;
                __nv_bfloat162 eB = *(__nv_bfloat162*)&sB;
                __nv_bfloat162 fA, fB;
                fA.x = __float2bfloat16(__bfloat162float(eA.x) * rL0);
                fA.y = __float2bfloat16(__bfloat162float(eA.y) * rL0);
                fB.x = __float2bfloat16(__bfloat162float(eB.x) * rL1);
                fB.y = __float2bfloat16(__bfloat162float(eB.y) * rL1);
                pa[ks][half * 2 + 0] = *(uint32_t*)&fA;
                pa[ks][half * 2 + 1] = *(uint32_t*)&fB;
            }
        }

        #pragma unroll
        for (int nt = 0; nt < 8; nt++) {
            #pragma unroll
            for (int ks = 0; ks < 4; ks++) {
                int l2 = lane & 15;
                uint32_t addr = kvb + (uint32_t)((ks * 16 + l2) * 144 + nt * 16);
                uint32_t b0, b1;
                ldsm_x2_t(b0, b1, addr);
                mma16816(o[nt][0], o[nt][1], o[nt][2], o[nt][3],
                         pa[ks][0], pa[ks][1], pa[ks][2], pa[ks][3], b0, b1);
            }
        }
    }

    const int qg0 = qt * 64;
    #pragma unroll
    for (int nt = 0; nt < 8; nt++) {
        const int colb = h * 64 + nt * 8 + (lane & 3) * 2;
        float2 vA = make_float2(bf16r(o[nt][0]), bf16r(o[nt][1]));
        float2 vB = make_float2(bf16r(o[nt][2]), bf16r(o[nt][3]));
        *(float2*)&g_attn[(size_t)(qg0 + rA) * EMB + colb]     = vA;
        *(float2*)&g_attn[(size_t)(qg0 + rA + 8) * EMB + colb] = vB;
    }
}

#define WGB_SMEM (18432)

__global__ __launch_bounds__(256) void attnB_kernel()
{
    extern __shared__ char dyn_smem[];
    const int wg   = threadIdx.x >> 7;
    const int wtid = threadIdx.x & 127;
    __nv_bfloat16* KV2 = (__nv_bfloat16*)(dyn_smem + wg * WGB_SMEM);
    const int h  = blockIdx.y;
    const int qt = wg ? (31 - (int)blockIdx.x) : (int)blockIdx.x;
    attnB_qtile(qt, h, KV2, wtid, wg + 1);
}

// ---------------------------------------------------------------------------
// Output projection, 2xTF32, 64m x 128n tiles + register prefetch — EXACT
// round-13/14/15 version (validated).
// ---------------------------------------------------------------------------
#define ASTR 36
#define BSTR 136

__global__ __launch_bounds__(256) void out_proj_tf32(
    const float* __restrict__ Wo, const float* __restrict__ bo,
    float* __restrict__ outp)
{
    extern __shared__ uint32_t dsm[];
    uint32_t* Ah = dsm;                    // [64][ASTR]
    uint32_t* Bh = Ah + 64 * ASTR;         // [32][BSTR]
    uint32_t* Bl = Bh + 32 * BSTR;

    const int tid = threadIdx.x, lane = tid & 31, warp = tid >> 5;
    const int wm = warp >> 2, wn = warp & 3;
    const int g = lane >> 2, t = lane & 3;
    const int bM = blockIdx.y * 64, bN = blockIdx.x * 128;

    const int a_row = tid >> 3, a_c = (tid & 7) * 4;
    const int a_row1 = (tid + 256) >> 3, a_c1 = ((tid + 256) & 7) * 4;
    float acc[2][4][4] = {};

    float4 pa0 = *(const float4*)(g_attn + (size_t)(bM + a_row) * EMB + a_c);
    float4 pa1 = *(const float4*)(g_attn + (size_t)(bM + a_row1) * EMB + a_c1);
    float4 pb[4];
    #pragma unroll
    for (int u = 0; u < 4; u++) {
        int idx = tid + u * 256;
        pb[u] = *(const float4*)(Wo + (size_t)(idx >> 5) * EMB + bN + (idx & 31) * 4);
    }

    for (int k0 = 0; k0 < EMB; k0 += 32) {
        {
            uint4 h;
            h.x = f2tf32(pa0.x); h.y = f2tf32(pa0.y);
            h.z = f2tf32(pa0.z); h.w = f2tf32(pa0.w);
            *(uint4*)&Ah[a_row * ASTR + a_c] = h;
            h.x = f2tf32(pa1.x); h.y = f2tf32(pa1.y);
            h.z = f2tf32(pa1.z); h.w = f2tf32(pa1.w);
            *(uint4*)&Ah[a_row1 * ASTR + a_c1] = h;
        }
        #pragma unroll
        for (int u = 0; u < 4; u++) {
            int idx = tid + u * 256;
            int kr = idx >> 5, c4 = (idx & 31) * 4;
            float4 v = pb[u];
            uint4 h, l;
            h.x = f2tf32(v.x); l.x = f2tf32(v.x - __uint_as_float(h.x));
            h.y = f2tf32(v.y); l.y = f2tf32(v.y - __uint_as_float(h.y));
            h.z = f2tf32(v.z); l.z = f2tf32(v.z - __uint_as_float(h.z));
            h.w = f2tf32(v.w); l.w = f2tf32(v.w - __uint_as_float(h.w));
            *(uint4*)&Bh[kr * BSTR + c4] = h;
            *(uint4*)&Bl[kr * BSTR + c4] = l;
        }
        __syncthreads();

        if (k0 + 32 < EMB) {
            pa0 = *(const float4*)(g_attn + (size_t)(bM + a_row) * EMB + k0 + 32 + a_c);
            pa1 = *(const float4*)(g_attn + (size_t)(bM + a_row1) * EMB + k0 + 32 + a_c1);
            #pragma unroll
            for (int u = 0; u < 4; u++) {
                int idx = tid + u * 256;
                pb[u] = *(const float4*)(Wo + (size_t)(k0 + 32 + (idx >> 5)) * EMB +
                                         bN + (idx & 31) * 4);
            }
        }

        #pragma unroll
        for (int ks = 0; ks < 4; ks++) {
            uint32_t ah[2][4], bh[4][2], bl[4][2];
            #pragma unroll
            for (int mi = 0; mi < 2; mi++) {
                int base = (wm * 32 + mi * 16 + g) * ASTR + ks * 8 + t;
                ah[mi][0] = Ah[base];
                ah[mi][1] = Ah[base + 8 * ASTR];
                ah[mi][2] = Ah[base + 4];
                ah[mi][3] = Ah[base + 8 * ASTR + 4];
            }
            #pragma unroll
            for (int nj = 0; nj < 4; nj++) {
                int base = (ks * 8 + t) * BSTR + wn * 32 + nj * 8 + g;
                bh[nj][0] = Bh[base];
                bh[nj][1] = Bh[base + 4 * BSTR];
                bl[nj][0] = Bl[base];
                bl[nj][1] = Bl[base + 4 * BSTR];
            }
            #pragma unroll
            for (int mi = 0; mi < 2; mi++)
                #pragma unroll
                for (int nj = 0; nj < 4; nj++) {
                    mma_tf32(acc[mi][nj], ah[mi], bh[nj]);
                    mma_tf32(acc[mi][nj], ah[mi], bl[nj]);
                }
        }
        __syncthreads();
    }

    #pragma unroll
    for (int mi = 0; mi < 2; mi++) {
        #pragma unroll
        for (int nj = 0; nj < 4; nj++) {
            int m0r = bM + wm * 32 + mi * 16 + g;
            int n   = bN + wn * 32 + nj * 8 + t * 2;
            float b0 = bo[n], b1 = bo[n + 1];
            float2 v0 = make_float2(acc[mi][nj][0] + b0, acc[mi][nj][1] + b1);
            float2 v1 = make_float2(acc[mi][nj][2] + b0, acc[mi][nj][3] + b1);
            *(float2*)&outp[(size_t)m0r * EMB + n]       = v0;
            *(float2*)&outp[(size_t)(m0r + 8) * EMB + n] = v1;
        }
    }
}

// ---------------------------------------------------------------------------

extern "C" void kernel_launch(void* const* d_in, const int* in_sizes, int n_in,
                              void* d_out, int out_size)
{
    const float* x  = (const float*)d_in[0];
    const float* Wq = (const float*)d_in[1];
    const float* bq = (const float*)d_in[2];
    const float* Wk = (const float*)d_in[3];
    const float* bk = (const float*)d_in[4];
    const float* Wv = (const float*)d_in[5];
    const float* bv = (const float*)d_in[6];
    const float* Wo = (const float*)d_in[7];
    const float* bo = (const float*)d_in[8];
    float* out = (float*)d_out;

    const int fusedA_smem = 2 * WGA_SMEM;                         // 57856 B
    const int attnB_smem  = 2 * WGB_SMEM;                         // 36864 B
    const int outp_smem   = (64 * ASTR + 32 * BSTR * 2) * 4;      // 44032 B
    cudaFuncSetAttribute(fused_attnA_projV,
                         cudaFuncAttributeMaxDynamicSharedMemorySize, fusedA_smem);
    cudaFuncSetAttribute(attnB_kernel,
                         cudaFuncAttributeMaxDynamicSharedMemorySize, attnB_smem);
    cudaFuncSetAttribute(out_proj_tf32,
                         cudaFuncAttributeMaxDynamicSharedMemorySize, outp_smem);

    proj_qk_kernel<<<dim3(EMB / 128, SEQ / 128, 2), 256>>>(x, Wq, bq, Wk, bk);
    fused_attnA_projV<<<384, 256, fusedA_smem>>>(x, Wv, bv);
    attnB_kernel<<<dim3(16, NH), 256, attnB_smem>>>();
    out_proj_tf32<<<dim3(EMB / 128, SEQ / 64), 256, outp_smem>>>(Wo, bo, out);
}

// round 17
// speedup vs baseline: 1.1050x; 1.1050x over previous
#include <cuda_runtime.h>
#include <cuda_bf16.h>
#include <math.h>
#include <stdint.h>

#define SEQ 2048
#define EMB 1024
#define NH  16
#define HD  64

typedef unsigned long long u64;

// Scratch (device globals — no allocation allowed)
__device__ __nv_bfloat16 g_Q[NH * SEQ * HD];
__device__ __nv_bfloat16 g_K[NH * SEQ * HD];
__device__ __nv_bfloat16 g_V[NH * SEQ * HD];
// g_S: TILED layout [NH][32 qt][32 kt][64*64], scores then exp values
__device__ __nv_bfloat16 g_S[(size_t)NH * SEQ * SEQ];
__device__ float g_attn[SEQ * EMB];

__device__ __forceinline__ float bf16r(float v) {
    return __bfloat162float(__float2bfloat16(v));
}
__device__ __forceinline__ uint32_t f2tf32(float x) {
    uint32_t r;
    asm("cvt.rna.tf32.f32 %0, %1;" : "=r"(r) : "f"(x));
    return r;
}

// ---------------- packed f32x2 fma (Blackwell FFMA2) ----------------
__device__ __forceinline__ void fma2(u64& d, u64 a, u64 b) {
    asm("fma.rn.f32x2 %0, %1, %2, %0;" : "+l"(d) : "l"(a), "l"(b));
}
__device__ __forceinline__ u64 bcast2(float v) {
    u64 r; asm("mov.b64 %0, {%1, %2};" : "=l"(r) : "f"(v), "f"(v)); return r;
}
__device__ __forceinline__ void unpack2(u64 p, float& lo, float& hi) {
    asm("mov.b64 {%0, %1}, %2;" : "=f"(lo), "=f"(hi) : "l"(p));
}

// ---------------- mma.sync helpers ----------------
__device__ __forceinline__ uint32_t smem_u32(const void* p) {
    return (uint32_t)__cvta_generic_to_shared(p);
}
__device__ __forceinline__ void ldsm_x4(uint32_t& a0, uint32_t& a1,
                                        uint32_t& a2, uint32_t& a3, uint32_t addr) {
    asm volatile("ldmatrix.sync.aligned.m8n8.x4.shared.b16 {%0,%1,%2,%3}, [%4];\n"
                 : "=r"(a0), "=r"(a1), "=r"(a2), "=r"(a3) : "r"(addr));
}
__device__ __forceinline__ void ldsm_x2(uint32_t& b0, uint32_t& b1, uint32_t addr) {
    asm volatile("ldmatrix.sync.aligned.m8n8.x2.shared.b16 {%0,%1}, [%2];\n"
                 : "=r"(b0), "=r"(b1) : "r"(addr));
}
__device__ __forceinline__ void ldsm_x2_t(uint32_t& b0, uint32_t& b1, uint32_t addr) {
    asm volatile("ldmatrix.sync.aligned.m8n8.x2.trans.shared.b16 {%0,%1}, [%2];\n"
                 : "=r"(b0), "=r"(b1) : "r"(addr));
}
__device__ __forceinline__ void mma16816(float& d0, float& d1, float& d2, float& d3,
                                         uint32_t a0, uint32_t a1, uint32_t a2, uint32_t a3,
                                         uint32_t b0, uint32_t b1) {
    asm volatile("mma.sync.aligned.m16n8k16.row.col.f32.bf16.bf16.f32 "
                 "{%0,%1,%2,%3},{%4,%5,%6,%7},{%8,%9},{%0,%1,%2,%3};\n"
                 : "+f"(d0), "+f"(d1), "+f"(d2), "+f"(d3)
                 : "r"(a0), "r"(a1), "r"(a2), "r"(a3), "r"(b0), "r"(b1));
}
__device__ __forceinline__ void mma_tf32(float* d, const uint32_t* a,
                                         const uint32_t* b) {
    asm volatile("mma.sync.aligned.m16n8k8.row.col.f32.tf32.tf32.f32 "
                 "{%0,%1,%2,%3},{%4,%5,%6,%7},{%8,%9},{%0,%1,%2,%3};\n"
                 : "+f"(d[0]), "+f"(d[1]), "+f"(d[2]), "+f"(d[3])
                 : "r"(a[0]), "r"(a[1]), "r"(a[2]), "r"(a[3]), "r"(b[0]), "r"(b[1]));
}

// ---------------- cp.async helpers ----------------
__device__ __forceinline__ void cp_async16(uint32_t smem_addr, const void* gptr) {
    asm volatile("cp.async.cg.shared.global [%0], [%1], 16;\n"
                 :: "r"(smem_addr), "l"(gptr));
}
__device__ __forceinline__ void cp_commit() {
    asm volatile("cp.async.commit_group;\n" ::: "memory");
}
__device__ __forceinline__ void cp_wait0() {
    asm volatile("cp.async.wait_group 0;\n" ::: "memory");
}
__device__ __forceinline__ void bar_sync(int id) {
    asm volatile("bar.sync %0, 128;\n" :: "r"(id) : "memory");
}

// ---------------------------------------------------------------------------
// Fused QKV projection — round-15 version (sequential-K FFMA2 chains,
// conflict-free B reads, Kc=8 double buffer, reg prefetch) with packed
// bf16x2 epilogue stores (same values, half the STGs).
// ---------------------------------------------------------------------------
__global__ __launch_bounds__(256) void proj_qkv_kernel(
    const float* __restrict__ x,
    const float* __restrict__ Wq, const float* __restrict__ bq,
    const float* __restrict__ Wk, const float* __restrict__ bk,
    const float* __restrict__ Wv, const float* __restrict__ bv)
{
    const float* W; const float* bias; __nv_bfloat16* out;
    if (blockIdx.z == 0)      { W = Wq; bias = bq; out = g_Q; }
    else if (blockIdx.z == 1) { W = Wk; bias = bk; out = g_K; }
    else                      { W = Wv; bias = bv; out = g_V; }

    __shared__ float As[2][8][128];
    __shared__ float Bs[2][8][128];
    const int tid = threadIdx.x;
    const int tx = tid & 15, ty = tid >> 4;
    const int bM = blockIdx.y * 128, bN = blockIdx.x * 128;

    const int ar = tid >> 1, ac = (tid & 1) * 4;
    const int br = tid >> 5, bc = (tid & 31) * 4;

    u64 acc2[8][4] = {};

    float4 pa = *(const float4*)(x + (size_t)(bM + ar) * EMB + ac);
    float4 pb = *(const float4*)(W + (size_t)br * EMB + bN + bc);

    for (int k0 = 0; k0 < EMB; k0 += 8) {
        const int b = (k0 >> 3) & 1;
        As[b][ac + 0][ar] = pa.x; As[b][ac + 1][ar] = pa.y;
        As[b][ac + 2][ar] = pa.z; As[b][ac + 3][ar] = pa.w;
        *(float4*)&Bs[b][br][bc] = pb;
        __syncthreads();

        if (k0 + 8 < EMB) {
            pa = *(const float4*)(x + (size_t)(bM + ar) * EMB + k0 + 8 + ac);
            pb = *(const float4*)(W + (size_t)(k0 + 8 + br) * EMB + bN + bc);
        }

        #pragma unroll
        for (int kk = 0; kk < 8; kk++) {
            float a[8];
            *(float4*)&a[0]  = *(float4*)&As[b][kk][ty * 8];
            *(float4*)&a[4]  = *(float4*)&As[b][kk][ty * 8 + 4];
            float4 b4a = *(float4*)&Bs[b][kk][tx * 4];
            float4 b4b = *(float4*)&Bs[b][kk][tx * 4 + 64];
            u64 bb2[4];
            bb2[0] = ((u64*)&b4a)[0];
            bb2[1] = ((u64*)&b4a)[1];
            bb2[2] = ((u64*)&b4b)[0];
            bb2[3] = ((u64*)&b4b)[1];
            #pragma unroll
            for (int i = 0; i < 8; i++) {
                u64 ai = bcast2(a[i]);
                #pragma unroll
                for (int jp = 0; jp < 4; jp++)
                    fma2(acc2[i][jp], ai, bb2[jp]);
            }
        }
    }

    #pragma unroll
    for (int i = 0; i < 8; i++) {
        int m = bM + ty * 8 + i;
        #pragma unroll
        for (int jp = 0; jp < 4; jp++) {
            float v0, v1;
            unpack2(acc2[i][jp], v0, v1);
            int n = bN + tx * 4 + (jp >> 1) * 64 + (jp & 1) * 2;
            __nv_bfloat162 pk;
            pk.x = __float2bfloat16(v0 + bias[n]);
            pk.y = __float2bfloat16(v1 + bias[n + 1]);
            // n ≡ 0 or 2 (mod 4) -> n and n+1 share the same head (n>>6)
            *(uint32_t*)&out[(size_t)(n >> 6) * SEQ * HD + (size_t)m * HD + (n & 63)] =
                *(uint32_t*)&pk;
        }
    }
}

// ---------------------------------------------------------------------------
// Causal attention — byte-identical to round 13/14/15 (bit-safe, tiled g_S).
// ---------------------------------------------------------------------------
__device__ __forceinline__ void stage_tile(uint32_t dst, const __nv_bfloat16* src,
                                           int wtid) {
    #pragma unroll
    for (int u = 0; u < 4; u++) {
        int idx = wtid + u * 128;
        int r = idx >> 3, s = idx & 7;
        cp_async16(dst + (uint32_t)((r * 72 + s * 8) * 2), src + r * 64 + s * 8);
    }
}

__device__ void attn_qtile(
    int qt, int h, __nv_bfloat16* Qs, __nv_bfloat16* KV2,
    float* mrow, float* Lrow, float* psum, int wtid, int barid)
{
    const int lane = wtid & 31;
    const int warp = wtid >> 5;
    const int r0   = warp * 16;

    const size_t qbase = ((size_t)h * SEQ + (size_t)qt * 64) * HD;
    const size_t tile0 = (((size_t)h * 32 + qt) * 32) * 4096;
    const __nv_bfloat16* Kh = g_K + (size_t)h * SEQ * HD;
    const __nv_bfloat16* Vh = g_V + (size_t)h * SEQ * HD;

    const uint32_t kvb0 = smem_u32(KV2);
    const uint32_t kvb1 = kvb0 + 64 * 72 * 2;

    for (int idx = wtid; idx < 64 * 8; idx += 128) {
        int r = idx >> 3, s = idx & 7;
        *(uint4*)&Qs[r * 72 + s * 8] = *(const uint4*)&g_Q[qbase + r * 64 + s * 8];
    }
    bar_sync(barid);

    uint32_t aq[4][4];
    {
        const uint32_t qb = smem_u32(Qs);
        #pragma unroll
        for (int ks = 0; ks < 4; ks++) {
            uint32_t addr = qb +
                (uint32_t)((r0 + (lane & 7) + ((lane >> 3) & 1) * 8) * 144 +
                           ((lane >> 4) * 16) + ks * 32);
            ldsm_x4(aq[ks][0], aq[ks][1], aq[ks][2], aq[ks][3], addr);
        }
    }

    // ================= PHASE 1: S -> g_S tiles, running row max ============
    float rm0 = -INFINITY, rm1 = -INFINITY;
    const int rA = r0 + (lane >> 2);

    stage_tile(kvb0, Kh, wtid);
    cp_commit();

    for (int kt = 0; kt <= qt; kt++) {
        cp_wait0();
        bar_sync(barid);
        const uint32_t kvb = (kt & 1) ? kvb1 : kvb0;
        if (kt < qt) {
            stage_tile((kt & 1) ? kvb0 : kvb1, Kh + (size_t)(kt + 1) * 64 * HD, wtid);
            cp_commit();
        }

        const size_t tb = tile0 + (size_t)kt * 4096;
        const bool diag = (kt == qt);
        #pragma unroll
        for (int nt = 0; nt < 8; nt++) {
            float c0 = 0.f, c1 = 0.f, c2 = 0.f, c3 = 0.f;
            #pragma unroll
            for (int ks = 0; ks < 4; ks++) {
                int l2 = lane & 15;
                uint32_t addr = kvb +
                    (uint32_t)((nt * 8 + (l2 & 7)) * 144 + (l2 >> 3) * 16 + ks * 32);
                uint32_t b0, b1;
                ldsm_x2(b0, b1, addr);
                mma16816(c0, c1, c2, c3,
                         aq[ks][0], aq[ks][1], aq[ks][2], aq[ks][3], b0, b1);
            }
            const int cc = nt * 8 + (lane & 3) * 2;
            float s00 = bf16r(c0) * 0.5f;
            float s01 = bf16r(c1) * 0.5f;
            float s10 = bf16r(c2) * 0.5f;
            float s11 = bf16r(c3) * 0.5f;
            if (diag) {
                if (cc     > rA)     s00 = -INFINITY;
                if (cc + 1 > rA)     s01 = -INFINITY;
                if (cc     > rA + 8) s10 = -INFINITY;
                if (cc + 1 > rA + 8) s11 = -INFINITY;
            }
            rm0 = fmaxf(rm0, fmaxf(s00, s01));
            rm1 = fmaxf(rm1, fmaxf(s10, s11));
            __nv_bfloat162 p0; p0.x = __float2bfloat16(s00); p0.y = __float2bfloat16(s01);
            __nv_bfloat162 p1; p1.x = __float2bfloat16(s10); p1.y = __float2bfloat16(s11);
            *(uint32_t*)&g_S[tb + (size_t)rA * 64 + cc]       = *(uint32_t*)&p0;
            *(uint32_t*)&g_S[tb + (size_t)(rA + 8) * 64 + cc] = *(uint32_t*)&p1;
        }
    }
    rm0 = fmaxf(rm0, __shfl_xor_sync(0xFFFFFFFFu, rm0, 1));
    rm0 = fmaxf(rm0, __shfl_xor_sync(0xFFFFFFFFu, rm0, 2));
    rm1 = fmaxf(rm1, __shfl_xor_sync(0xFFFFFFFFu, rm1, 1));
    rm1 = fmaxf(rm1, __shfl_xor_sync(0xFFFFFFFFu, rm1, 2));
    if ((lane & 3) == 0) {
        mrow[rA]     = rm0;
        mrow[rA + 8] = rm1;
    }
    bar_sync(barid);

    // ====== PHASE 2: e -> g_S (same value/order chain) =====================
    for (int rb = 0; rb < 64; rb += 32) {
        const int r = rb + (wtid >> 2), seg = wtid & 3;
        const float m = mrow[r];
        float part = 0.f;
        for (int ktt = 0; ktt <= qt; ktt++) {
            __nv_bfloat16* tp = &g_S[tile0 + (size_t)ktt * 4096 + (size_t)r * 64];
            #pragma unroll 4
            for (int c = seg; c < 64; c += 4) {
                float s = __bfloat162float(tp[c]);
                float t = bf16r(s - m);
                float e = bf16r(expf(t));
                part += e;
                tp[c] = __float2bfloat16(e);
            }
        }
        psum[r * 4 + seg] = part;
    }
    bar_sync(barid);
    if (wtid < 64) {
        float L32 = ((psum[wtid * 4 + 0] + psum[wtid * 4 + 1]) +
                      psum[wtid * 4 + 2]) + psum[wtid * 4 + 3];
        Lrow[wtid] = bf16r(L32);
    }
    bar_sync(barid);

    // ================= PHASE 3: p = bf16(e * (1/L)), O = P @ V =============
    const float rL0 = 1.0f / Lrow[rA];
    const float rL1 = 1.0f / Lrow[rA + 8];

    float o[8][4];
    #pragma unroll
    for (int nt = 0; nt < 8; nt++)
        #pragma unroll
        for (int i = 0; i < 4; i++) o[nt][i] = 0.f;

    stage_tile(kvb0, Vh, wtid);
    cp_commit();

    for (int kt = 0; kt <= qt; kt++) {
        cp_wait0();
        bar_sync(barid);
        const uint32_t kvb = (kt & 1) ? kvb1 : kvb0;
        if (kt < qt) {
            stage_tile((kt & 1) ? kvb0 : kvb1, Vh + (size_t)(kt + 1) * 64 * HD, wtid);
            cp_commit();
        }

        const size_t tb  = tile0 + (size_t)kt * 4096;
        const size_t rowA = tb + (size_t)rA * 64;
        const size_t rowB = tb + (size_t)(rA + 8) * 64;

        uint32_t pa[4][4];
        #pragma unroll
        for (int ks = 0; ks < 4; ks++) {
            const int col = ks * 16 + (lane & 3) * 2;
            #pragma unroll
            for (int half = 0; half < 2; half++) {
                uint32_t sA = *(const uint32_t*)&g_S[rowA + col + half * 8];
                uint32_t sB = *(const uint32_t*)&g_S[rowB + col + half * 8];
                __nv_bfloat162 eA = *(__nv_bfloat162*)&sA;
                __nv_bfloat162 eB = *(__nv_bfloat162*)&sB;
                __nv_bfloat162 fA, fB;
                fA.x = __float2bfloat16(__bfloat162float(eA.x) * rL0);
                fA.y = __float2bfloat16(__bfloat162float(eA.y) * rL0);
                fB.x = __float2bfloat16(__bfloat162float(eB.x) * rL1);
                fB.y = __float2bfloat16(__bfloat162float(eB.y) * rL1);
                pa[ks][half * 2 + 0] = *(uint32_t*)&fA;
                pa[ks][half * 2 + 1] = *(uint32_t*)&fB;
            }
        }

        #pragma unroll
        for (int nt = 0; nt < 8; nt++) {
            #pragma unroll
            for (int ks = 0; ks < 4; ks++) {
                int l2 = lane & 15;
                uint32_t addr = kvb + (uint32_t)((ks * 16 + l2) * 144 + nt * 16);
                uint32_t b0, b1;
                ldsm_x2_t(b0, b1, addr);
                mma16816(o[nt][0], o[nt][1], o[nt][2], o[nt][3],
                         pa[ks][0], pa[ks][1], pa[ks][2], pa[ks][3], b0, b1);
            }
        }
    }

    const int qg0 = qt * 64;
    #pragma unroll
    for (int nt = 0; nt < 8; nt++) {
        const int colb = h * 64 + nt * 8 + (lane & 3) * 2;
        float2 vA = make_float2(bf16r(o[nt][0]), bf16r(o[nt][1]));
        float2 vB = make_float2(bf16r(o[nt][2]), bf16r(o[nt][3]));
        *(float2*)&g_attn[(size_t)(qg0 + rA) * EMB + colb]     = vA;
        *(float2*)&g_attn[(size_t)(qg0 + rA + 8) * EMB + colb] = vB;
    }
}

// per-WG smem partition: Qs 9216 B, KV2 18432 B, mrow 256, Lrow 256, psum 1024
#define WG_SMEM (9216 + 18432 + 256 + 256 + 1024)   // 29184 B

__global__ __launch_bounds__(256) void attn_kernel()
{
    extern __shared__ char asm_smem[];
    const int wg   = threadIdx.x >> 7;     // 0 or 1
    const int wtid = threadIdx.x & 127;

    char* base = asm_smem + wg * WG_SMEM;
    __nv_bfloat16* Qs  = (__nv_bfloat16*)base;
    __nv_bfloat16* KV2 = (__nv_bfloat16*)(base + 9216);
    float* mrow = (float*)(base + 9216 + 18432);
    float* Lrow = mrow + 64;
    float* psum = Lrow + 64;

    const int h  = blockIdx.y;
    const int qt = wg ? (31 - (int)blockIdx.x) : (int)blockIdx.x;
    attn_qtile(qt, h, Qs, KV2, mrow, Lrow, psum, wtid, wg + 1);
}

// ---------------------------------------------------------------------------
// Output projection, 2xTF32, 64m x 128n tiles, register prefetch, NOW with
// double-buffered smem and a single __syncthreads per k-chunk.
// Per-output arithmetic (ks order, hh then hl) unchanged -> bit-safe.
// ---------------------------------------------------------------------------
#define ASTR 36
#define BSTR 136
#define OP_BUF (64 * ASTR + 32 * BSTR * 2)   // uint32 words per buffer

__global__ __launch_bounds__(256) void out_proj_tf32(
    const float* __restrict__ Wo, const float* __restrict__ bo,
    float* __restrict__ outp)
{
    extern __shared__ uint32_t dsm[];

    const int tid = threadIdx.x, lane = tid & 31, warp = tid >> 5;
    const int wm = warp >> 2, wn = warp & 3;
    const int g = lane >> 2, t = lane & 3;
    const int bM = blockIdx.y * 64, bN = blockIdx.x * 128;

    const int a_row = tid >> 3, a_c = (tid & 7) * 4;
    const int a_row1 = (tid + 256) >> 3, a_c1 = ((tid + 256) & 7) * 4;
    float acc[2][4][4] = {};

    float4 pa0 = *(const float4*)(g_attn + (size_t)(bM + a_row) * EMB + a_c);
    float4 pa1 = *(const float4*)(g_attn + (size_t)(bM + a_row1) * EMB + a_c1);
    float4 pb[4];
    #pragma unroll
    for (int u = 0; u < 4; u++) {
        int idx = tid + u * 256;
        pb[u] = *(const float4*)(Wo + (size_t)(idx >> 5) * EMB + bN + (idx & 31) * 4);
    }

    for (int k0 = 0; k0 < EMB; k0 += 32) {
        const int bsel = (k0 >> 5) & 1;
        uint32_t* Ah = dsm + bsel * OP_BUF;
        uint32_t* Bh = Ah + 64 * ASTR;
        uint32_t* Bl = Bh + 32 * BSTR;

        {
            uint4 h;
            h.x = f2tf32(pa0.x); h.y = f2tf32(pa0.y);
            h.z = f2tf32(pa0.z); h.w = f2tf32(pa0.w);
            *(uint4*)&Ah[a_row * ASTR + a_c] = h;
            h.x = f2tf32(pa1.x); h.y = f2tf32(pa1.y);
            h.z = f2tf32(pa1.z); h.w = f2tf32(pa1.w);
            *(uint4*)&Ah[a_row1 * ASTR + a_c1] = h;
        }
        #pragma unroll
        for (int u = 0; u < 4; u++) {
            int idx = tid + u * 256;
            int kr = idx >> 5, c4 = (idx & 31) * 4;
            float4 v = pb[u];
            uint4 h, l;
            h.x = f2tf32(v.x); l.x = f2tf32(v.x - __uint_as_float(h.x));
            h.y = f2tf32(v.y); l.y = f2tf32(v.y - __uint_as_float(h.y));
            h.z = f2tf32(v.z); l.z = f2tf32(v.z - __uint_as_float(h.z));
            h.w = f2tf32(v.w); l.w = f2tf32(v.w - __uint_as_float(h.w));
            *(uint4*)&Bh[kr * BSTR + c4] = h;
            *(uint4*)&Bl[kr * BSTR + c4] = l;
        }
        __syncthreads();

        if (k0 + 32 < EMB) {
            pa0 = *(const float4*)(g_attn + (size_t)(bM + a_row) * EMB + k0 + 32 + a_c);
            pa1 = *(const float4*)(g_attn + (size_t)(bM + a_row1) * EMB + k0 + 32 + a_c1);
            #pragma unroll
            for (int u = 0; u < 4; u++) {
                int idx = tid + u * 256;
                pb[u] = *(const float4*)(Wo + (size_t)(k0 + 32 + (idx >> 5)) * EMB +
                                         bN + (idx & 31) * 4);
            }
        }

        #pragma unroll
        for (int ks = 0; ks < 4; ks++) {
            uint32_t ah[2][4], bh[4][2], bl[4][2];
            #pragma unroll
            for (int mi = 0; mi < 2; mi++) {
                int base = (wm * 32 + mi * 16 + g) * ASTR + ks * 8 + t;
                ah[mi][0] = Ah[base];
                ah[mi][1] = Ah[base + 8 * ASTR];
                ah[mi][2] = Ah[base + 4];
                ah[mi][3] = Ah[base + 8 * ASTR + 4];
            }
            #pragma unroll
            for (int nj = 0; nj < 4; nj++) {
                int base = (ks * 8 + t) * BSTR + wn * 32 + nj * 8 + g;
                bh[nj][0] = Bh[base];
                bh[nj][1] = Bh[base + 4 * BSTR];
                bl[nj][0] = Bl[base];
                bl[nj][1] = Bl[base + 4 * BSTR];
            }
            #pragma unroll
            for (int mi = 0; mi < 2; mi++)
                #pragma unroll
                for (int nj = 0; nj < 4; nj++) {
                    mma_tf32(acc[mi][nj], ah[mi], bh[nj]);
                    mma_tf32(acc[mi][nj], ah[mi], bl[nj]);
                }
        }
        // single sync per iteration: next iteration writes the other buffer.
    }

    #pragma unroll
    for (int mi = 0; mi < 2; mi++) {
        #pragma unroll
        for (int nj = 0; nj < 4; nj++) {
            int m0r = bM + wm * 32 + mi * 16 + g;
            int n   = bN + wn * 32 + nj * 8 + t * 2;
            float b0 = bo[n], b1 = bo[n + 1];
            float2 v0 = make_float2(acc[mi][nj][0] + b0, acc[mi][nj][1] + b1);
            float2 v1 = make_float2(acc[mi][nj][2] + b0, acc[mi][nj][3] + b1);
            *(float2*)&outp[(size_t)m0r * EMB + n]       = v0;
            *(float2*)&outp[(size_t)(m0r + 8) * EMB + n] = v1;
        }
    }
}

// ---------------------------------------------------------------------------

extern "C" void kernel_launch(void* const* d_in, const int* in_sizes, int n_in,
                              void* d_out, int out_size)
{
    const float* x  = (const float*)d_in[0];
    const float* Wq = (const float*)d_in[1];
    const float* bq = (const float*)d_in[2];
    const float* Wk = (const float*)d_in[3];
    const float* bk = (const float*)d_in[4];
    const float* Wv = (const float*)d_in[5];
    const float* bv = (const float*)d_in[6];
    const float* Wo = (const float*)d_in[7];
    const float* bo = (const float*)d_in[8];
    float* out = (float*)d_out;

    const int attn_smem = 2 * WG_SMEM;                            // 58368 B
    const int outp_smem = 2 * OP_BUF * 4;                         // 88064 B
    cudaFuncSetAttribute(attn_kernel,
                         cudaFuncAttributeMaxDynamicSharedMemorySize, attn_smem);
    cudaFuncSetAttribute(out_proj_tf32,
                         cudaFuncAttributeMaxDynamicSharedMemorySize, outp_smem);

    proj_qkv_kernel<<<dim3(EMB / 128, SEQ / 128, 3), 256>>>(x, Wq, bq, Wk, bk, Wv, bv);
    attn_kernel<<<dim3(16, NH), 256, attn_smem>>>();
    out_proj_tf32<<<dim3(EMB / 128, SEQ / 64), 256, outp_smem>>>(Wo, bo, out);
}